// round 15
// baseline (speedup 1.0000x reference)
#include <cuda_runtime.h>
#include <cuda_bf16.h>
#include <cstdint>

#define MDIM 10000
#define NDIM 512
#define KDIM 512
#define AST  40     // smem row stride in bf16 (32 + 8 pad, ldmatrix-safe)
#define MAXE 204800

// byte offsets inside one pipeline buffer (tile 64x128, BK=32)
#define A_HI  0
#define A_LO  (64 * AST * 2)               // 5120
#define B_HI  (2 * 64 * AST * 2)           // 10240
#define B_LO  (B_HI + 128 * AST * 2)       // 20480
#define BUFB  (B_HI + 2 * 128 * AST * 2)   // 30720 B per buffer
#define GEMM_SMEM (2 * BUFB)               // 61440 B

// ---------------- device scratch (static; no allocation) --------------------
__device__ float         g_ZW[(size_t)MDIM * NDIM];    // Z @ W, fp32
__device__ float         g_part[MAXE];                 // partial edge dots
__device__ __nv_bfloat16 g_WThi[(size_t)NDIM * KDIM];  // W^T hi split [n][k]
__device__ __nv_bfloat16 g_WTlo[(size_t)NDIM * KDIM];  // W^T lo split [n][k]
__device__ int g_idx64;

// ---------------------------------------------------------------------------
__device__ __forceinline__ void mma_bf16(float* c, const uint32_t* a, const uint32_t* b) {
    asm volatile(
        "mma.sync.aligned.m16n8k16.row.col.f32.bf16.bf16.f32 "
        "{%0,%1,%2,%3}, {%4,%5,%6,%7}, {%8,%9}, {%0,%1,%2,%3};"
        : "+f"(c[0]), "+f"(c[1]), "+f"(c[2]), "+f"(c[3])
        : "r"(a[0]), "r"(a[1]), "r"(a[2]), "r"(a[3]), "r"(b[0]), "r"(b[1]));
}

__device__ __forceinline__ void ldsm_x4(uint32_t* r, uint32_t addr) {
    asm volatile("ldmatrix.sync.aligned.m8n8.x4.shared.b16 {%0,%1,%2,%3}, [%4];"
                 : "=r"(r[0]), "=r"(r[1]), "=r"(r[2]), "=r"(r[3]) : "r"(addr));
}

// ---------------------------------------------------------------------------
// Transpose W into bf16 hi/lo splits [n][k] + edge-index dtype detect
// (int64 <=> all odd 32-bit words of the first 128 entries are zero).
// ---------------------------------------------------------------------------
__global__ void wt_convert_kernel(const float* __restrict__ W,
                                  const unsigned int* __restrict__ e32) {
    __shared__ float t[32][33];
    const int bx = blockIdx.x, by = blockIdx.y;
    const int tx = (int)threadIdx.x, ty = (int)threadIdx.y;   // 32 x 8

#pragma unroll
    for (int j = 0; j < 4; j++)
        t[ty + j * 8][tx] = W[(size_t)(by * 32 + ty + j * 8) * NDIM + bx * 32 + tx];
    __syncthreads();

#pragma unroll
    for (int j = 0; j < 4; j++) {
        int n = bx * 32 + ty + j * 8;
        int k = by * 32 + tx;
        float v = t[tx][ty + j * 8];
        __nv_bfloat16 h = __float2bfloat16(v);
        g_WThi[(size_t)n * KDIM + k] = h;
        g_WTlo[(size_t)n * KDIM + k] = __float2bfloat16(v - __bfloat162float(h));
    }

    if (bx == 0 && by == 0 && ty == 0) {
        int bad = 0;
        for (int i = tx; i < 128; i += 32)
            if (e32[2 * i + 1] != 0u) bad = 1;
        unsigned m = __ballot_sync(0xFFFFFFFFu, bad);
        if (tx == 0) g_idx64 = (m == 0u);
    }
}

// ---------------------------------------------------------------------------
// ZW = Z @ W via split-bf16 mma.sync (3 passes; lo*lo dropped).
// Block tile 64x128, BK=32, ping-pong double buffer, 2 CTAs/SM.
// bnoff selects the N-half (0 -> cols 0-255, 2 -> cols 256-511).
// ---------------------------------------------------------------------------
__global__ __launch_bounds__(256, 2)
void gemm_kernel(const float* __restrict__ Z, int bnoff) {
    extern __shared__ char smem[];
    const int bm = blockIdx.y * 64;
    const int bn = (blockIdx.x + bnoff) * 128;
    const int tid = (int)threadIdx.x;
    const int lane = tid & 31, wid = tid >> 5;
    const int wm = (wid & 1) * 32;
    const int wn = (wid >> 1) * 32;
    const int g = lane >> 2, tg = lane & 3;

    const uint32_t sb = (uint32_t)__cvta_generic_to_shared(smem);

    uint32_t aoff[2];
#pragma unroll
    for (int mi = 0; mi < 2; mi++)
        aoff[mi] = (uint32_t)(((wm + mi * 16 + (lane & 15)) * AST + (lane >> 4) * 8) * 2);
    uint32_t boff[2];
    {
        int q = lane >> 3, l8 = lane & 7;
        int n_l = (q >> 1) * 8 + l8;
        int k_l = (q & 1) * 8;
#pragma unroll
        for (int nc = 0; nc < 2; nc++)
            boff[nc] = (uint32_t)(((wn + nc * 16 + n_l) * AST + k_l) * 2);
    }

    float acc[2][4][4];
#pragma unroll
    for (int mi = 0; mi < 2; mi++)
#pragma unroll
        for (int ni = 0; ni < 4; ni++)
#pragma unroll
            for (int j = 0; j < 4; j++) acc[mi][ni][j] = 0.0f;

    float4 areg[2];
    uint4  bhreg[2], blreg[2];

    auto ldg = [&](int k0) {
#pragma unroll
        for (int i = 0; i < 2; i++) {
            int flat = tid + 256 * i;
            int row = flat >> 3, c4 = (flat & 7) * 4;
            int grow = bm + row;
            areg[i] = (grow < MDIM)
                ? *(const float4*)(Z + (size_t)grow * KDIM + k0 + c4)
                : make_float4(0.f, 0.f, 0.f, 0.f);
        }
#pragma unroll
        for (int i = 0; i < 2; i++) {
            int flat = tid + 256 * i;
            int row = flat >> 2, c8 = (flat & 3) * 8;
            size_t gi = (size_t)(bn + row) * KDIM + k0 + c8;
            bhreg[i] = *(const uint4*)(g_WThi + gi);
            blreg[i] = *(const uint4*)(g_WTlo + gi);
        }
    };

    auto sts = [&](int buf) {
        char* bp = smem + buf * BUFB;
#pragma unroll
        for (int i = 0; i < 2; i++) {
            int flat = tid + 256 * i;
            int row = flat >> 3, c4 = (flat & 7) * 4;
            int eo = row * AST + c4;
            float4 v = areg[i];
            __nv_bfloat16 h0 = __float2bfloat16(v.x);
            __nv_bfloat16 h1 = __float2bfloat16(v.y);
            __nv_bfloat16 h2 = __float2bfloat16(v.z);
            __nv_bfloat16 h3 = __float2bfloat16(v.w);
            __nv_bfloat162* ph = (__nv_bfloat162*)(bp + A_HI + eo * 2);
            ph[0] = __nv_bfloat162(h0, h1);
            ph[1] = __nv_bfloat162(h2, h3);
            __nv_bfloat162* pl = (__nv_bfloat162*)(bp + A_LO + eo * 2);
            pl[0] = __nv_bfloat162(__float2bfloat16(v.x - __bfloat162float(h0)),
                                   __float2bfloat16(v.y - __bfloat162float(h1)));
            pl[1] = __nv_bfloat162(__float2bfloat16(v.z - __bfloat162float(h2)),
                                   __float2bfloat16(v.w - __bfloat162float(h3)));
        }
#pragma unroll
        for (int i = 0; i < 2; i++) {
            int flat = tid + 256 * i;
            int row = flat >> 2, c8 = (flat & 3) * 8;
            int eo = row * AST + c8;
            *(uint4*)(bp + B_HI + eo * 2) = bhreg[i];
            *(uint4*)(bp + B_LO + eo * 2) = blreg[i];
        }
    };

    ldg(0);
    sts(0);
    __syncthreads();

    const int NIT = KDIM / 32;                 // 16 stages
    for (int it = 0; it < NIT; it++) {
        if (it + 1 < NIT) ldg((it + 1) * 32);

        const uint32_t cb = sb + (uint32_t)((it & 1) * BUFB);
#pragma unroll
        for (int kk = 0; kk < 32; kk += 16) {
            uint32_t Ahi[2][4], Alo[2][4], Bhi[2][4], Blo[2][4];
#pragma unroll
            for (int mi = 0; mi < 2; mi++) {
                ldsm_x4(Ahi[mi], cb + A_HI + aoff[mi] + kk * 2);
                ldsm_x4(Alo[mi], cb + A_LO + aoff[mi] + kk * 2);
            }
#pragma unroll
            for (int nc = 0; nc < 2; nc++) {
                ldsm_x4(Bhi[nc], cb + B_HI + boff[nc] + kk * 2);
                ldsm_x4(Blo[nc], cb + B_LO + boff[nc] + kk * 2);
            }
#pragma unroll
            for (int mi = 0; mi < 2; mi++)
#pragma unroll
                for (int ni = 0; ni < 4; ni++) {
                    const uint32_t* bh = &Bhi[ni >> 1][(ni & 1) * 2];
                    const uint32_t* bl = &Blo[ni >> 1][(ni & 1) * 2];
                    mma_bf16(acc[mi][ni], Ahi[mi], bh);
                    mma_bf16(acc[mi][ni], Ahi[mi], bl);
                    mma_bf16(acc[mi][ni], Alo[mi], bh);
                }
        }

        if (it + 1 < NIT) {
            sts((it + 1) & 1);
            __syncthreads();
        }
    }

#pragma unroll
    for (int mi = 0; mi < 2; mi++)
#pragma unroll
        for (int ni = 0; ni < 4; ni++) {
            int row = bm + wm + mi * 16 + g;
            int col = bn + wn + ni * 8 + tg * 2;
            if (row < MDIM)
                *(float2*)&g_ZW[(size_t)row * NDIM + col] =
                    make_float2(acc[mi][ni][0], acc[mi][ni][1]);
            if (row + 8 < MDIM)
                *(float2*)&g_ZW[(size_t)(row + 8) * NDIM + col] =
                    make_float2(acc[mi][ni][2], acc[mi][ni][3]);
        }
}

// ---------------------------------------------------------------------------
// Edge scoring, split in column halves so half 0 can overlap GEMM_N1.
//   half 0: partial dot over cols [0,256)   -> g_part[e]
//   half 1: dot over cols [256,512) + g_part -> sigmoid -> out[e]
// ---------------------------------------------------------------------------
__device__ __forceinline__ void load_edge(const void* edges, int E, int e,
                                          int& r, int& c) {
    if (g_idx64) {
        const long long* p = (const long long*)edges;
        r = (int)p[e];
        c = (int)p[(size_t)E + e];
    } else {
        const int* p = (const int*)edges;
        r = p[e];
        c = p[(size_t)E + e];
    }
}

__global__ __launch_bounds__(256)
void edge_half_kernel(const float* __restrict__ Z,
                      const void* __restrict__ edges,
                      float* __restrict__ out, int E, int half) {
    int w = (int)((blockIdx.x * 256u + threadIdx.x) >> 5);
    int lane = (int)(threadIdx.x & 31);
    if (w >= E) return;
    int r, c;
    load_edge(edges, E, w, r, c);

    const float4* a = (const float4*)(g_ZW + (size_t)r * NDIM + half * 256);
    const float4* b = (const float4*)(Z + (size_t)c * NDIM + half * 256);
    float sum = 0.0f;
#pragma unroll
    for (int i = 0; i < 2; i++) {
        float4 x = a[lane + 32 * i];
        float4 y = b[lane + 32 * i];
        sum = fmaf(x.x, y.x, fmaf(x.y, y.y, fmaf(x.z, y.z, fmaf(x.w, y.w, sum))));
    }
#pragma unroll
    for (int o = 16; o; o >>= 1)
        sum += __shfl_xor_sync(0xFFFFFFFFu, sum, o);
    if (lane == 0) {
        if (half == 0)
            g_part[w] = sum;
        else
            out[w] = 1.0f / (1.0f + expf(-(g_part[w] + sum)));
    }
}

// Fallback: full dot in one kernel (used if E > MAXE).
__global__ __launch_bounds__(256)
void edge_kernel(const float* __restrict__ Z,
                 const void* __restrict__ edges,
                 float* __restrict__ out, int E) {
    int w = (int)((blockIdx.x * 256u + threadIdx.x) >> 5);
    int lane = (int)(threadIdx.x & 31);
    if (w >= E) return;
    int r, c;
    load_edge(edges, E, w, r, c);

    const float4* a = (const float4*)(g_ZW + (size_t)r * NDIM);
    const float4* b = (const float4*)(Z + (size_t)c * NDIM);
    float sum = 0.0f;
#pragma unroll
    for (int i = 0; i < 4; i++) {
        float4 x = a[lane + 32 * i];
        float4 y = b[lane + 32 * i];
        sum = fmaf(x.x, y.x, fmaf(x.y, y.y, fmaf(x.z, y.z, fmaf(x.w, y.w, sum))));
    }
#pragma unroll
    for (int o = 16; o; o >>= 1)
        sum += __shfl_xor_sync(0xFFFFFFFFu, sum, o);
    if (lane == 0)
        out[w] = 1.0f / (1.0f + expf(-sum));
}

// ---------------------------------------------------------------------------
extern "C" void kernel_launch(void* const* d_in, const int* in_sizes, int n_in,
                              void* d_out, int out_size) {
    const float* z_drug = (const float*)d_in[0];   // [10000, 512] f32
    const float* weight = (const float*)d_in[1];   // [512, 512]   f32
    const void*  edges  = d_in[2];                 // [2, E] int64 or int32
    float* out = (float*)d_out;
    const int E = out_size;

    static cudaStream_t s2 = nullptr;
    static cudaEvent_t  ev0 = nullptr, ev1 = nullptr;
    if (!s2) {
        cudaFuncSetAttribute(gemm_kernel,
                             cudaFuncAttributeMaxDynamicSharedMemorySize,
                             GEMM_SMEM);
        cudaStreamCreateWithFlags(&s2, cudaStreamNonBlocking);
        cudaEventCreateWithFlags(&ev0, cudaEventDisableTiming);
        cudaEventCreateWithFlags(&ev1, cudaEventDisableTiming);
    }

    const dim3 ghalf(2, (MDIM + 63) / 64);         // (2, 157) per N-half
    const int eblocks = (E + 7) / 8;

    wt_convert_kernel<<<dim3(16, 16), dim3(32, 8)>>>(weight,
                                                     (const unsigned int*)edges);

    if (E <= MAXE) {
        // N-half 0 on default stream
        gemm_kernel<<<ghalf, 256, GEMM_SMEM>>>(z_drug, 0);
        cudaEventRecord(ev0, 0);
        // N-half 1 on s2, serialized after half 0 -> overlaps edge half 0
        cudaStreamWaitEvent(s2, ev0, 0);
        gemm_kernel<<<ghalf, 256, GEMM_SMEM, s2>>>(z_drug, 2);
        cudaEventRecord(ev1, s2);
        // edge half 0 (cols 0-255) overlaps GEMM N-half 1
        edge_half_kernel<<<eblocks, 256>>>(z_drug, edges, out, E, 0);
        // join, then edge half 1 finishes the dot + sigmoid
        cudaStreamWaitEvent(0, ev1, 0);
        edge_half_kernel<<<eblocks, 256>>>(z_drug, edges, out, E, 1);
    } else {
        gemm_kernel<<<ghalf, 256, GEMM_SMEM>>>(z_drug, 0);
        gemm_kernel<<<ghalf, 256, GEMM_SMEM>>>(z_drug, 2);
        edge_kernel<<<eblocks, 256>>>(z_drug, edges, out, E);
    }
}

// round 16
// speedup vs baseline: 1.6166x; 1.6166x over previous
#include <cuda_runtime.h>
#include <cuda_bf16.h>
#include <cstdint>

#define MDIM 10000
#define NDIM 512
#define KDIM 512
#define AST  40     // smem row stride in bf16 (32 + 8 pad, ldmatrix-safe)

#define MT_TOTAL 157        // ceil(10000/64) row tiles
#define MT_HALF0 79         // tiles 0..78  -> rows [0, 5056)
#define M_SPLIT  (MT_HALF0 * 64)

// byte offsets inside one pipeline buffer (tile 64x128, BK=32)
#define A_HI  0
#define A_LO  (64 * AST * 2)               // 5120
#define B_HI  (2 * 64 * AST * 2)           // 10240
#define B_LO  (B_HI + 128 * AST * 2)       // 20480
#define BUFB  (B_HI + 2 * 128 * AST * 2)   // 30720 B per buffer
#define GEMM_SMEM (2 * BUFB)               // 61440 B -> 2 CTAs/SM

// ---------------- device scratch (static; no allocation) --------------------
__device__ float         g_ZW[(size_t)MDIM * NDIM];    // Z @ W, fp32
__device__ __nv_bfloat16 g_WThi[(size_t)NDIM * KDIM];  // W^T hi split [n][k]
__device__ __nv_bfloat16 g_WTlo[(size_t)NDIM * KDIM];  // W^T lo split [n][k]
__device__ int g_idx64;

// ---------------------------------------------------------------------------
__device__ __forceinline__ void mma_bf16(float* c, const uint32_t* a, const uint32_t* b) {
    asm volatile(
        "mma.sync.aligned.m16n8k16.row.col.f32.bf16.bf16.f32 "
        "{%0,%1,%2,%3}, {%4,%5,%6,%7}, {%8,%9}, {%0,%1,%2,%3};"
        : "+f"(c[0]), "+f"(c[1]), "+f"(c[2]), "+f"(c[3])
        : "r"(a[0]), "r"(a[1]), "r"(a[2]), "r"(a[3]), "r"(b[0]), "r"(b[1]));
}

__device__ __forceinline__ void ldsm_x4(uint32_t* r, uint32_t addr) {
    asm volatile("ldmatrix.sync.aligned.m8n8.x4.shared.b16 {%0,%1,%2,%3}, [%4];"
                 : "=r"(r[0]), "=r"(r[1]), "=r"(r[2]), "=r"(r[3]) : "r"(addr));
}

// ---------------------------------------------------------------------------
// Transpose W into bf16 hi/lo splits [n][k] + edge-index dtype detect
// (int64 <=> all odd 32-bit words of the first 128 entries are zero).
// ---------------------------------------------------------------------------
__global__ void wt_convert_kernel(const float* __restrict__ W,
                                  const unsigned int* __restrict__ e32) {
    __shared__ float t[32][33];
    const int bx = blockIdx.x, by = blockIdx.y;
    const int tx = (int)threadIdx.x, ty = (int)threadIdx.y;   // 32 x 8

#pragma unroll
    for (int j = 0; j < 4; j++)
        t[ty + j * 8][tx] = W[(size_t)(by * 32 + ty + j * 8) * NDIM + bx * 32 + tx];
    __syncthreads();

#pragma unroll
    for (int j = 0; j < 4; j++) {
        int n = bx * 32 + ty + j * 8;
        int k = by * 32 + tx;
        float v = t[tx][ty + j * 8];
        __nv_bfloat16 h = __float2bfloat16(v);
        g_WThi[(size_t)n * KDIM + k] = h;
        g_WTlo[(size_t)n * KDIM + k] = __float2bfloat16(v - __bfloat162float(h));
    }

    if (bx == 0 && by == 0 && ty == 0) {
        int bad = 0;
        for (int i = tx; i < 128; i += 32)
            if (e32[2 * i + 1] != 0u) bad = 1;
        unsigned m = __ballot_sync(0xFFFFFFFFu, bad);
        if (tx == 0) g_idx64 = (m == 0u);
    }
}

// ---------------------------------------------------------------------------
// ZW = Z @ W via split-bf16 mma.sync (3 passes; lo*lo dropped).
// Block tile 64x128, BK=32, ping-pong double buffer, 2 CTAs/SM.  (r9 verbatim
// + bmtile row-tile offset so the grid can be split by M halves.)
// ---------------------------------------------------------------------------
__global__ __launch_bounds__(256, 2)
void gemm_kernel(const float* __restrict__ Z, int bmtile) {
    extern __shared__ char smem[];
    const int bm = (bmtile + (int)blockIdx.y) * 64;
    const int bn = blockIdx.x * 128;
    const int tid = (int)threadIdx.x;
    const int lane = tid & 31, wid = tid >> 5;
    const int wm = (wid & 1) * 32;
    const int wn = (wid >> 1) * 32;
    const int g = lane >> 2, tg = lane & 3;

    const uint32_t sb = (uint32_t)__cvta_generic_to_shared(smem);

    uint32_t aoff[2];
#pragma unroll
    for (int mi = 0; mi < 2; mi++)
        aoff[mi] = (uint32_t)(((wm + mi * 16 + (lane & 15)) * AST + (lane >> 4) * 8) * 2);
    uint32_t boff[2];
    {
        int q = lane >> 3, l8 = lane & 7;
        int n_l = (q >> 1) * 8 + l8;
        int k_l = (q & 1) * 8;
#pragma unroll
        for (int nc = 0; nc < 2; nc++)
            boff[nc] = (uint32_t)(((wn + nc * 16 + n_l) * AST + k_l) * 2);
    }

    float acc[2][4][4];
#pragma unroll
    for (int mi = 0; mi < 2; mi++)
#pragma unroll
        for (int ni = 0; ni < 4; ni++)
#pragma unroll
            for (int j = 0; j < 4; j++) acc[mi][ni][j] = 0.0f;

    float4 areg[2];
    uint4  bhreg[2], blreg[2];

    auto ldg = [&](int k0) {
#pragma unroll
        for (int i = 0; i < 2; i++) {
            int flat = tid + 256 * i;
            int row = flat >> 3, c4 = (flat & 7) * 4;
            int grow = bm + row;
            areg[i] = (grow < MDIM)
                ? *(const float4*)(Z + (size_t)grow * KDIM + k0 + c4)
                : make_float4(0.f, 0.f, 0.f, 0.f);
        }
#pragma unroll
        for (int i = 0; i < 2; i++) {
            int flat = tid + 256 * i;
            int row = flat >> 2, c8 = (flat & 3) * 8;
            size_t gi = (size_t)(bn + row) * KDIM + k0 + c8;
            bhreg[i] = *(const uint4*)(g_WThi + gi);
            blreg[i] = *(const uint4*)(g_WTlo + gi);
        }
    };

    auto sts = [&](int buf) {
        char* bp = smem + buf * BUFB;
#pragma unroll
        for (int i = 0; i < 2; i++) {
            int flat = tid + 256 * i;
            int row = flat >> 3, c4 = (flat & 7) * 4;
            int eo = row * AST + c4;
            float4 v = areg[i];
            __nv_bfloat16 h0 = __float2bfloat16(v.x);
            __nv_bfloat16 h1 = __float2bfloat16(v.y);
            __nv_bfloat16 h2 = __float2bfloat16(v.z);
            __nv_bfloat16 h3 = __float2bfloat16(v.w);
            __nv_bfloat162* ph = (__nv_bfloat162*)(bp + A_HI + eo * 2);
            ph[0] = __nv_bfloat162(h0, h1);
            ph[1] = __nv_bfloat162(h2, h3);
            __nv_bfloat162* pl = (__nv_bfloat162*)(bp + A_LO + eo * 2);
            pl[0] = __nv_bfloat162(__float2bfloat16(v.x - __bfloat162float(h0)),
                                   __float2bfloat16(v.y - __bfloat162float(h1)));
            pl[1] = __nv_bfloat162(__float2bfloat16(v.z - __bfloat162float(h2)),
                                   __float2bfloat16(v.w - __bfloat162float(h3)));
        }
#pragma unroll
        for (int i = 0; i < 2; i++) {
            int flat = tid + 256 * i;
            int row = flat >> 2, c8 = (flat & 3) * 8;
            int eo = row * AST + c8;
            *(uint4*)(bp + B_HI + eo * 2) = bhreg[i];
            *(uint4*)(bp + B_LO + eo * 2) = blreg[i];
        }
    };

    ldg(0);
    sts(0);
    __syncthreads();

    const int NIT = KDIM / 32;                 // 16 stages
    for (int it = 0; it < NIT; it++) {
        if (it + 1 < NIT) ldg((it + 1) * 32);

        const uint32_t cb = sb + (uint32_t)((it & 1) * BUFB);
#pragma unroll
        for (int kk = 0; kk < 32; kk += 16) {
            uint32_t Ahi[2][4], Alo[2][4], Bhi[2][4], Blo[2][4];
#pragma unroll
            for (int mi = 0; mi < 2; mi++) {
                ldsm_x4(Ahi[mi], cb + A_HI + aoff[mi] + kk * 2);
                ldsm_x4(Alo[mi], cb + A_LO + aoff[mi] + kk * 2);
            }
#pragma unroll
            for (int nc = 0; nc < 2; nc++) {
                ldsm_x4(Bhi[nc], cb + B_HI + boff[nc] + kk * 2);
                ldsm_x4(Blo[nc], cb + B_LO + boff[nc] + kk * 2);
            }
#pragma unroll
            for (int mi = 0; mi < 2; mi++)
#pragma unroll
                for (int ni = 0; ni < 4; ni++) {
                    const uint32_t* bh = &Bhi[ni >> 1][(ni & 1) * 2];
                    const uint32_t* bl = &Blo[ni >> 1][(ni & 1) * 2];
                    mma_bf16(acc[mi][ni], Ahi[mi], bh);
                    mma_bf16(acc[mi][ni], Ahi[mi], bl);
                    mma_bf16(acc[mi][ni], Alo[mi], bh);
                }
        }

        if (it + 1 < NIT) {
            sts((it + 1) & 1);
            __syncthreads();
        }
    }

#pragma unroll
    for (int mi = 0; mi < 2; mi++)
#pragma unroll
        for (int ni = 0; ni < 4; ni++) {
            int row = bm + wm + mi * 16 + g;
            int col = bn + wn + ni * 8 + tg * 2;
            if (row < MDIM)
                *(float2*)&g_ZW[(size_t)row * NDIM + col] =
                    make_float2(acc[mi][ni][0], acc[mi][ni][1]);
            if (row + 8 < MDIM)
                *(float2*)&g_ZW[(size_t)(row + 8) * NDIM + col] =
                    make_float2(acc[mi][ni][2], acc[mi][ni][3]);
        }
}

// ---------------------------------------------------------------------------
// Per-edge score, restricted to edges whose r lies in [rlo, rhi): full-length
// dot (r9 form) + 2-instruction range filter.  Edges outside exit immediately.
// ---------------------------------------------------------------------------
__device__ __forceinline__ void load_edge(const void* edges, int E, int e,
                                          int& r, int& c) {
    if (g_idx64) {
        const long long* p = (const long long*)edges;
        r = (int)p[e];
        c = (int)p[(size_t)E + e];
    } else {
        const int* p = (const int*)edges;
        r = p[e];
        c = p[(size_t)E + e];
    }
}

__global__ __launch_bounds__(256)
void edge_kernel(const float* __restrict__ Z,
                 const void* __restrict__ edges,
                 float* __restrict__ out, int E, int rlo, int rhi) {
    int w = (int)((blockIdx.x * 256u + threadIdx.x) >> 5);
    int lane = (int)(threadIdx.x & 31);
    if (w >= E) return;
    int r, c;
    load_edge(edges, E, w, r, c);
    if ((unsigned)(r - rlo) >= (unsigned)(rhi - rlo)) return;

    const float4* a = (const float4*)(g_ZW + (size_t)r * NDIM);
    const float4* b = (const float4*)(Z + (size_t)c * NDIM);
    float sum = 0.0f;
#pragma unroll
    for (int i = 0; i < 4; i++) {
        float4 x = a[lane + 32 * i];
        float4 y = b[lane + 32 * i];
        sum = fmaf(x.x, y.x, fmaf(x.y, y.y, fmaf(x.z, y.z, fmaf(x.w, y.w, sum))));
    }
#pragma unroll
    for (int o = 16; o; o >>= 1)
        sum += __shfl_xor_sync(0xFFFFFFFFu, sum, o);
    if (lane == 0)
        out[w] = 1.0f / (1.0f + expf(-sum));
}

// ---------------------------------------------------------------------------
extern "C" void kernel_launch(void* const* d_in, const int* in_sizes, int n_in,
                              void* d_out, int out_size) {
    const float* z_drug = (const float*)d_in[0];   // [10000, 512] f32
    const float* weight = (const float*)d_in[1];   // [512, 512]   f32
    const void*  edges  = d_in[2];                 // [2, E] int64 or int32
    float* out = (float*)d_out;
    const int E = out_size;

    static cudaStream_t s2 = nullptr;
    static cudaEvent_t  ev0 = nullptr, ev1 = nullptr;
    if (!s2) {
        cudaFuncSetAttribute(gemm_kernel,
                             cudaFuncAttributeMaxDynamicSharedMemorySize,
                             GEMM_SMEM);
        cudaStreamCreateWithFlags(&s2, cudaStreamNonBlocking);
        cudaEventCreateWithFlags(&ev0, cudaEventDisableTiming);
        cudaEventCreateWithFlags(&ev1, cudaEventDisableTiming);
    }

    const int eblocks = (E + 7) / 8;

    wt_convert_kernel<<<dim3(16, 16), dim3(32, 8)>>>(weight,
                                                     (const unsigned int*)edges);

    // GEMM M-half 0: row tiles [0, 79) -> rows [0, 5056)
    gemm_kernel<<<dim3(NDIM / 128, MT_HALF0), 256, GEMM_SMEM>>>(z_drug, 0);
    cudaEventRecord(ev0, 0);

    // GEMM M-half 1 on s2 (after half 0): rows [5056, 10000)
    cudaStreamWaitEvent(s2, ev0, 0);
    gemm_kernel<<<dim3(NDIM / 128, MT_TOTAL - MT_HALF0), 256, GEMM_SMEM, s2>>>(
        z_drug, MT_HALF0);
    cudaEventRecord(ev1, s2);

    // edges with r < 5056 overlap GEMM M-half 1
    edge_kernel<<<eblocks, 256>>>(z_drug, edges, out, E, 0, M_SPLIT);

    // join, then the remaining edges
    cudaStreamWaitEvent(0, ev1, 0);
    edge_kernel<<<eblocks, 256>>>(z_drug, edges, out, E, M_SPLIT, MDIM);
}

// round 17
// speedup vs baseline: 1.7788x; 1.1004x over previous
#include <cuda_runtime.h>
#include <cuda_bf16.h>
#include <cstdint>

#define MDIM 10000
#define NDIM 512
#define KDIM 512
#define AST  40     // smem row stride in bf16 (32 + 8 pad, ldmatrix-safe)

// byte offsets inside one pipeline buffer (tile 64x128, BK=32)
#define A_HI  0
#define A_LO  (64 * AST * 2)               // 5120
#define B_HI  (2 * 64 * AST * 2)           // 10240
#define B_LO  (B_HI + 128 * AST * 2)       // 20480
#define BUFB  (B_HI + 2 * 128 * AST * 2)   // 30720 B per buffer
#define GEMM_SMEM (2 * BUFB)               // 61440 B -> 2 CTAs/SM

// ---------------- device scratch (static; no allocation) --------------------
__device__ float         g_ZW[(size_t)MDIM * NDIM];    // Z @ W, fp32
__device__ __nv_bfloat16 g_WThi[(size_t)NDIM * KDIM];  // W^T hi split [n][k]
__device__ __nv_bfloat16 g_WTlo[(size_t)NDIM * KDIM];  // W^T lo split [n][k]
__device__ int g_idx64;

// ---------------------------------------------------------------------------
__device__ __forceinline__ void mma_bf16(float* c, const uint32_t* a, const uint32_t* b) {
    asm volatile(
        "mma.sync.aligned.m16n8k16.row.col.f32.bf16.bf16.f32 "
        "{%0,%1,%2,%3}, {%4,%5,%6,%7}, {%8,%9}, {%0,%1,%2,%3};"
        : "+f"(c[0]), "+f"(c[1]), "+f"(c[2]), "+f"(c[3])
        : "r"(a[0]), "r"(a[1]), "r"(a[2]), "r"(a[3]), "r"(b[0]), "r"(b[1]));
}

__device__ __forceinline__ void ldsm_x4(uint32_t* r, uint32_t addr) {
    asm volatile("ldmatrix.sync.aligned.m8n8.x4.shared.b16 {%0,%1,%2,%3}, [%4];"
                 : "=r"(r[0]), "=r"(r[1]), "=r"(r[2]), "=r"(r[3]) : "r"(addr));
}

// ---------------------------------------------------------------------------
// Transpose W into bf16 hi/lo splits [n][k] + edge-index dtype detect
// (int64 <=> all odd 32-bit words of the first 128 entries are zero).
// ---------------------------------------------------------------------------
__global__ void wt_convert_kernel(const float* __restrict__ W,
                                  const unsigned int* __restrict__ e32) {
    __shared__ float t[32][33];
    const int bx = blockIdx.x, by = blockIdx.y;
    const int tx = (int)threadIdx.x, ty = (int)threadIdx.y;   // 32 x 8

#pragma unroll
    for (int j = 0; j < 4; j++)
        t[ty + j * 8][tx] = W[(size_t)(by * 32 + ty + j * 8) * NDIM + bx * 32 + tx];
    __syncthreads();

#pragma unroll
    for (int j = 0; j < 4; j++) {
        int n = bx * 32 + ty + j * 8;
        int k = by * 32 + tx;
        float v = t[tx][ty + j * 8];
        __nv_bfloat16 h = __float2bfloat16(v);
        g_WThi[(size_t)n * KDIM + k] = h;
        g_WTlo[(size_t)n * KDIM + k] = __float2bfloat16(v - __bfloat162float(h));
    }

    if (bx == 0 && by == 0 && ty == 0) {
        int bad = 0;
        for (int i = tx; i < 128; i += 32)
            if (e32[2 * i + 1] != 0u) bad = 1;
        unsigned m = __ballot_sync(0xFFFFFFFFu, bad);
        if (tx == 0) g_idx64 = (m == 0u);
    }
}

// ---------------------------------------------------------------------------
// ZW = Z @ W via split-bf16 mma.sync (3 passes; lo*lo dropped).
// Block tile 64x128, BK=32, ping-pong double buffer, 2 CTAs/SM.
// r9 structure; MMA passes hoisted outermost so consecutive MMAs hit
// DIFFERENT accumulators (8 independent MMAs between same-acc reuses,
// hiding HMMA RAW latency).
// ---------------------------------------------------------------------------
__global__ __launch_bounds__(256, 2)
void gemm_kernel(const float* __restrict__ Z) {
    extern __shared__ char smem[];
    const int bm = blockIdx.y * 64;
    const int bn = blockIdx.x * 128;
    const int tid = (int)threadIdx.x;
    const int lane = tid & 31, wid = tid >> 5;
    const int wm = (wid & 1) * 32;
    const int wn = (wid >> 1) * 32;
    const int g = lane >> 2, tg = lane & 3;

    const uint32_t sb = (uint32_t)__cvta_generic_to_shared(smem);

    uint32_t aoff[2];
#pragma unroll
    for (int mi = 0; mi < 2; mi++)
        aoff[mi] = (uint32_t)(((wm + mi * 16 + (lane & 15)) * AST + (lane >> 4) * 8) * 2);
    uint32_t boff[2];
    {
        int q = lane >> 3, l8 = lane & 7;
        int n_l = (q >> 1) * 8 + l8;
        int k_l = (q & 1) * 8;
#pragma unroll
        for (int nc = 0; nc < 2; nc++)
            boff[nc] = (uint32_t)(((wn + nc * 16 + n_l) * AST + k_l) * 2);
    }

    float acc[2][4][4];
#pragma unroll
    for (int mi = 0; mi < 2; mi++)
#pragma unroll
        for (int ni = 0; ni < 4; ni++)
#pragma unroll
            for (int j = 0; j < 4; j++) acc[mi][ni][j] = 0.0f;

    float4 areg[2];
    uint4  bhreg[2], blreg[2];

    auto ldg = [&](int k0) {
#pragma unroll
        for (int i = 0; i < 2; i++) {
            int flat = tid + 256 * i;
            int row = flat >> 3, c4 = (flat & 7) * 4;
            int grow = bm + row;
            areg[i] = (grow < MDIM)
                ? *(const float4*)(Z + (size_t)grow * KDIM + k0 + c4)
                : make_float4(0.f, 0.f, 0.f, 0.f);
        }
#pragma unroll
        for (int i = 0; i < 2; i++) {
            int flat = tid + 256 * i;
            int row = flat >> 2, c8 = (flat & 3) * 8;
            size_t gi = (size_t)(bn + row) * KDIM + k0 + c8;
            bhreg[i] = *(const uint4*)(g_WThi + gi);
            blreg[i] = *(const uint4*)(g_WTlo + gi);
        }
    };

    auto sts = [&](int buf) {
        char* bp = smem + buf * BUFB;
#pragma unroll
        for (int i = 0; i < 2; i++) {
            int flat = tid + 256 * i;
            int row = flat >> 3, c4 = (flat & 7) * 4;
            int eo = row * AST + c4;
            float4 v = areg[i];
            __nv_bfloat16 h0 = __float2bfloat16(v.x);
            __nv_bfloat16 h1 = __float2bfloat16(v.y);
            __nv_bfloat16 h2 = __float2bfloat16(v.z);
            __nv_bfloat16 h3 = __float2bfloat16(v.w);
            __nv_bfloat162* ph = (__nv_bfloat162*)(bp + A_HI + eo * 2);
            ph[0] = __nv_bfloat162(h0, h1);
            ph[1] = __nv_bfloat162(h2, h3);
            __nv_bfloat162* pl = (__nv_bfloat162*)(bp + A_LO + eo * 2);
            pl[0] = __nv_bfloat162(__float2bfloat16(v.x - __bfloat162float(h0)),
                                   __float2bfloat16(v.y - __bfloat162float(h1)));
            pl[1] = __nv_bfloat162(__float2bfloat16(v.z - __bfloat162float(h2)),
                                   __float2bfloat16(v.w - __bfloat162float(h3)));
        }
#pragma unroll
        for (int i = 0; i < 2; i++) {
            int flat = tid + 256 * i;
            int row = flat >> 2, c8 = (flat & 3) * 8;
            int eo = row * AST + c8;
            *(uint4*)(bp + B_HI + eo * 2) = bhreg[i];
            *(uint4*)(bp + B_LO + eo * 2) = blreg[i];
        }
    };

    ldg(0);
    sts(0);
    __syncthreads();

    const int NIT = KDIM / 32;                 // 16 stages
    for (int it = 0; it < NIT; it++) {
        if (it + 1 < NIT) ldg((it + 1) * 32);

        const uint32_t cb = sb + (uint32_t)((it & 1) * BUFB);
#pragma unroll
        for (int kk = 0; kk < 32; kk += 16) {
            uint32_t Ahi[2][4], Alo[2][4], Bhi[2][4], Blo[2][4];
#pragma unroll
            for (int mi = 0; mi < 2; mi++) {
                ldsm_x4(Ahi[mi], cb + A_HI + aoff[mi] + kk * 2);
                ldsm_x4(Alo[mi], cb + A_LO + aoff[mi] + kk * 2);
            }
#pragma unroll
            for (int nc = 0; nc < 2; nc++) {
                ldsm_x4(Bhi[nc], cb + B_HI + boff[nc] + kk * 2);
                ldsm_x4(Blo[nc], cb + B_LO + boff[nc] + kk * 2);
            }
            // Pass 1: Ahi * Bhi over all 8 accumulators (independent MMAs)
#pragma unroll
            for (int mi = 0; mi < 2; mi++)
#pragma unroll
                for (int ni = 0; ni < 4; ni++)
                    mma_bf16(acc[mi][ni], Ahi[mi], &Bhi[ni >> 1][(ni & 1) * 2]);
            // Pass 2: Ahi * Blo
#pragma unroll
            for (int mi = 0; mi < 2; mi++)
#pragma unroll
                for (int ni = 0; ni < 4; ni++)
                    mma_bf16(acc[mi][ni], Ahi[mi], &Blo[ni >> 1][(ni & 1) * 2]);
            // Pass 3: Alo * Bhi
#pragma unroll
            for (int mi = 0; mi < 2; mi++)
#pragma unroll
                for (int ni = 0; ni < 4; ni++)
                    mma_bf16(acc[mi][ni], Alo[mi], &Bhi[ni >> 1][(ni & 1) * 2]);
        }

        if (it + 1 < NIT) {
            sts((it + 1) & 1);
            __syncthreads();
        }
    }

#pragma unroll
    for (int mi = 0; mi < 2; mi++)
#pragma unroll
        for (int ni = 0; ni < 4; ni++) {
            int row = bm + wm + mi * 16 + g;
            int col = bn + wn + ni * 8 + tg * 2;
            if (row < MDIM)
                *(float2*)&g_ZW[(size_t)row * NDIM + col] =
                    make_float2(acc[mi][ni][0], acc[mi][ni][1]);
            if (row + 8 < MDIM)
                *(float2*)&g_ZW[(size_t)(row + 8) * NDIM + col] =
                    make_float2(acc[mi][ni][2], acc[mi][ni][3]);
        }
}

// ---------------------------------------------------------------------------
// Per-edge score: one warp per edge (fastest measured form).
// ---------------------------------------------------------------------------
__device__ __forceinline__ void load_edge(const void* edges, int E, int e,
                                          int& r, int& c) {
    if (g_idx64) {
        const long long* p = (const long long*)edges;
        r = (int)p[e];
        c = (int)p[(size_t)E + e];
    } else {
        const int* p = (const int*)edges;
        r = p[e];
        c = p[(size_t)E + e];
    }
}

__global__ __launch_bounds__(256)
void edge_kernel(const float* __restrict__ Z,
                 const void* __restrict__ edges,
                 float* __restrict__ out, int E) {
    int w = (int)((blockIdx.x * 256u + threadIdx.x) >> 5);
    int lane = (int)(threadIdx.x & 31);
    if (w >= E) return;
    int r, c;
    load_edge(edges, E, w, r, c);

    const float4* a = (const float4*)(g_ZW + (size_t)r * NDIM);
    const float4* b = (const float4*)(Z + (size_t)c * NDIM);
    float sum = 0.0f;
#pragma unroll
    for (int i = 0; i < 4; i++) {
        float4 x = a[lane + 32 * i];
        float4 y = b[lane + 32 * i];
        sum = fmaf(x.x, y.x, fmaf(x.y, y.y, fmaf(x.z, y.z, fmaf(x.w, y.w, sum))));
    }
#pragma unroll
    for (int o = 16; o; o >>= 1)
        sum += __shfl_xor_sync(0xFFFFFFFFu, sum, o);
    if (lane == 0)
        out[w] = 1.0f / (1.0f + expf(-sum));
}

// ---------------------------------------------------------------------------
extern "C" void kernel_launch(void* const* d_in, const int* in_sizes, int n_in,
                              void* d_out, int out_size) {
    const float* z_drug = (const float*)d_in[0];   // [10000, 512] f32
    const float* weight = (const float*)d_in[1];   // [512, 512]   f32
    const void*  edges  = d_in[2];                 // [2, E] int64 or int32
    float* out = (float*)d_out;
    const int E = out_size;

    static int smem_set = 0;
    if (!smem_set) {
        cudaFuncSetAttribute(gemm_kernel,
                             cudaFuncAttributeMaxDynamicSharedMemorySize,
                             GEMM_SMEM);
        smem_set = 1;
    }

    wt_convert_kernel<<<dim3(16, 16), dim3(32, 8)>>>(weight,
                                                     (const unsigned int*)edges);
    gemm_kernel<<<dim3(NDIM / 128, (MDIM + 63) / 64), 256, GEMM_SMEM>>>(z_drug);
    edge_kernel<<<(E + 7) / 8, 256>>>(z_drug, edges, out, E);
}